// round 16
// baseline (speedup 1.0000x reference)
#include <cuda_runtime.h>
#include <cuda_fp16.h>
#include <cstdint>

// ============================================================================
// QConv2D quantum conv via baseline-PTX fp16 mma.sync (HMMA) GEMM.
//   Kernel 1 (grid 4 x 512): build 64x64 unitary U (register statevector,
//   warp per column), emit B[128x64] fp16 PRE-PACKED in mma fragment layout.
//   B rows interleaved: 2s=Re U[s,:], 2s+1=Im U[s,:].
//   Kernel 2 (CTA = 64 patches, 128 threads, 5 CTAs/SM): two INDEPENDENT
//   32-patch warp-pairs (named 64-thread barriers only — no __syncthreads).
//   A = patch fp16 via smem+ldmatrix; B fragments via direct LDG.128
//   (L1-resident). C[64x128] = A*B^T (fp32 accum). Epilogue: probs,
//   factorized Walsh, deferred normalization by ||f||^2.
// ============================================================================

#define N_QUBITS 6
#define OH 63
#define OHW 3969
#define NPATCH (128 * OHW)     // 508032
#define SWZ(o) ((o) ^ (((o) >> 3) & 0x70))

__device__ uint4 g_Bfrag[1024];   // [ni][k][bt][lane] -> 16 KB

__device__ __forceinline__ uint32_t smem_u32(const void* p) {
    uint32_t a;
    asm("{ .reg .u64 t; cvta.to.shared.u64 t, %1; cvt.u32.u64 %0, t; }"
        : "=r"(a) : "l"(p));
    return a;
}
__device__ __forceinline__ void ldmx4(uint32_t* r, uint32_t addr) {
    asm volatile("ldmatrix.sync.aligned.m8n8.x4.shared.b16 {%0,%1,%2,%3}, [%4];"
                 : "=r"(r[0]), "=r"(r[1]), "=r"(r[2]), "=r"(r[3]) : "r"(addr));
}
__device__ __forceinline__ void mma_f16(float* c, const uint32_t* a, const uint32_t* b) {
    asm volatile(
        "mma.sync.aligned.m16n8k16.row.col.f32.f16.f16.f32 "
        "{%0,%1,%2,%3}, {%4,%5,%6,%7}, {%8,%9}, {%0,%1,%2,%3};"
        : "+f"(c[0]), "+f"(c[1]), "+f"(c[2]), "+f"(c[3])
        : "r"(a[0]), "r"(a[1]), "r"(a[2]), "r"(a[3]), "r"(b[0]), "r"(b[1]));
}
#define PAIR_BAR(id) asm volatile("bar.sync %0, 64;" :: "r"(id) : "memory")

__device__ __forceinline__ float2 cmad(float2 u, float2 a, float2 v, float2 b) {
    float2 r;
    r.x = u.x * a.x - u.y * a.y + v.x * b.x - v.y * b.y;
    r.y = u.x * a.y + u.y * a.x + v.x * b.y + v.y * b.x;
    return r;
}

// ----------------------------------------------------------------------------
// Kernel 1: build U + emit fragment-packed B.
// grid=4 (one per 16-col k-chunk), block=512 (16 warps = 16 columns).
// ----------------------------------------------------------------------------
__global__ __launch_bounds__(512) void build_unitary_kernel(const float* __restrict__ w) {
    __shared__ float gt[12][8];
    __shared__ __half sBL[128][17];   // [B row n][k local 0..15], padded
    const int t = threadIdx.x;
    if (t < 12) {
        int l = t / 6, q = t % 6;
        float phi   = w[(l * 6 + q) * 3 + 0];
        float theta = w[(l * 6 + q) * 3 + 1];
        float omega = w[(l * 6 + q) * 3 + 2];
        float s2, c2; sincosf(0.5f * theta, &s2, &c2);
        float sap, cap; sincosf(-0.5f * (phi + omega), &sap, &cap);
        float sam, cam; sincosf(-0.5f * (phi - omega), &sam, &cam);
        gt[t][0] =  cap * c2; gt[t][1] =  sap * c2;   // u00
        gt[t][2] = -cam * s2; gt[t][3] =  sam * s2;   // u01
        gt[t][4] =  cam * s2; gt[t][5] =  sam * s2;   // u10
        gt[t][6] =  cap * c2; gt[t][7] = -sap * c2;   // u11
    }
    __syncthreads();

    const int lane = t & 31;
    const int wid  = t >> 5;                  // local column 0..15
    const int col  = blockIdx.x * 16 + wid;   // global column (k index)

    float2 s0 = make_float2((2 * lane     == col) ? 1.f : 0.f, 0.f);
    float2 s1 = make_float2((2 * lane + 1 == col) ? 1.f : 0.f, 0.f);

    for (int rep = 0; rep < 2; rep++) {
        for (int l = 0; l < 2; l++) {
            for (int q = 0; q < N_QUBITS; q++) {
                const float* g = gt[l * 6 + q];
                float2 u00 = {g[0], g[1]}, u01 = {g[2], g[3]};
                float2 u10 = {g[4], g[5]}, u11 = {g[6], g[7]};
                int m = 1 << (5 - q);
                if (m == 1) {
                    float2 a = s0, b = s1;
                    s0 = cmad(u00, a, u01, b);
                    s1 = cmad(u10, a, u11, b);
                } else {
                    int d = m >> 1;
                    float2 p0, p1;
                    p0.x = __shfl_xor_sync(0xffffffffu, s0.x, d);
                    p0.y = __shfl_xor_sync(0xffffffffu, s0.y, d);
                    p1.x = __shfl_xor_sync(0xffffffffu, s1.x, d);
                    p1.y = __shfl_xor_sync(0xffffffffu, s1.y, d);
                    if (lane & d) {
                        s0 = cmad(u10, p0, u11, s0);
                        s1 = cmad(u10, p1, u11, s1);
                    } else {
                        s0 = cmad(u00, s0, u01, p0);
                        s1 = cmad(u00, s1, u01, p1);
                    }
                }
            }
            int r = l + 1;
            for (int q = 0; q < N_QUBITS; q++) {
                int tq = (q + r) % N_QUBITS;
                int mc = 1 << (5 - q);
                int mt = 1 << (5 - tq);
                if (mt == 1) {
                    if (lane & (mc >> 1)) { float2 tmp = s0; s0 = s1; s1 = tmp; }
                } else {
                    int d = mt >> 1;
                    if (mc == 1) {
                        float2 t1;
                        t1.x = __shfl_xor_sync(0xffffffffu, s1.x, d);
                        t1.y = __shfl_xor_sync(0xffffffffu, s1.y, d);
                        s1 = t1;
                    } else {
                        float2 t0, t1;
                        t0.x = __shfl_xor_sync(0xffffffffu, s0.x, d);
                        t0.y = __shfl_xor_sync(0xffffffffu, s0.y, d);
                        t1.x = __shfl_xor_sync(0xffffffffu, s1.x, d);
                        t1.y = __shfl_xor_sync(0xffffffffu, s1.y, d);
                        if (lane & (mc >> 1)) { s0 = t0; s1 = t1; }
                    }
                }
            }
        }
    }
    // B rows: n = 2s + (0:Re, 1:Im); lane holds states 2L, 2L+1
    sBL[4 * lane + 0][wid] = __float2half(s0.x);
    sBL[4 * lane + 1][wid] = __float2half(s0.y);
    sBL[4 * lane + 2][wid] = __float2half(s1.x);
    sBL[4 * lane + 3][wid] = __float2half(s1.y);
    __syncthreads();

    // emit fragments for this k-chunk (kc = blockIdx.x): 256 uint4
    if (t < 256) {
        const int L  = t & 31;
        const int bt = (t >> 5) & 3;
        const int ni = t >> 7;
        const int kc = blockIdx.x;
        const int n0 = ni * 64 + bt * 16 + (L >> 2);
        const int kk = 2 * (L & 3);
        __half2 b0t0 = {sBL[n0][kk],         sBL[n0][kk + 1]};
        __half2 b1t0 = {sBL[n0][kk + 8],     sBL[n0][kk + 9]};
        __half2 b0t1 = {sBL[n0 + 8][kk],     sBL[n0 + 8][kk + 1]};
        __half2 b1t1 = {sBL[n0 + 8][kk + 8], sBL[n0 + 8][kk + 9]};
        g_Bfrag[((ni * 4 + kc) * 4 + bt) * 32 + L] =
            make_uint4(*reinterpret_cast<uint32_t*>(&b0t0),
                       *reinterpret_cast<uint32_t*>(&b1t0),
                       *reinterpret_cast<uint32_t*>(&b0t1),
                       *reinterpret_cast<uint32_t*>(&b1t1));
    }
}

// ----------------------------------------------------------------------------
// Kernel 2: HMMA GEMM + epilogue. 128 threads = 2 independent warp-pairs,
// 32 patches per pair, 5 CTAs/SM. B fragments via direct LDG.128.
// ----------------------------------------------------------------------------
#define SM_A  0            //  8 KB: 64 rows x 128 B
#define SM_SSQ 8192        // float[64] = 256 B
#define SM_SZ  8448        // float[2][64][6] = 3072 B
#define SM_TOTAL 11520

__global__ __launch_bounds__(128, 5)
void qconv_kernel(const float* __restrict__ x, float* __restrict__ out) {
    extern __shared__ char smem[];
    const uint32_t sb = smem_u32(smem);
    float* sSsq = reinterpret_cast<float*>(smem + SM_SSQ);
    float* sZ   = reinterpret_cast<float*>(smem + SM_SZ);   // [ni][row][6]
    const int tid  = threadIdx.x;
    const int pair = tid >> 6;            // 0..1 (= mi)

    // ---- load phase: thread = (patch p = tid>>1, half h = tid&1 -> 2 channels)
    {
        const int p  = tid >> 1;              // 0..63
        const int h  = tid & 1;
        const int pi = blockIdx.x * 64 + p;
        const int b   = pi / OHW;
        const int rem = pi - b * OHW;
        const int oy  = rem / OH;
        const int ox  = rem - oy * OH;
        const float* xb = x + (((b * 4 + 2 * h) * 128) + 2 * oy) * 128 + 2 * ox;

        float ssq = 0.f;
        #pragma unroll
        for (int c2 = 0; c2 < 2; c2++) {
            #pragma unroll
            for (int ky2 = 0; ky2 < 2; ky2++) {
                const float* rA = xb + c2 * 16384 + (2 * ky2) * 128;
                float2 P0 = *reinterpret_cast<const float2*>(rA);
                float2 P1 = *reinterpret_cast<const float2*>(rA + 2);
                float2 P2 = *reinterpret_cast<const float2*>(rA + 128);
                float2 P3 = *reinterpret_cast<const float2*>(rA + 130);
                ssq += P0.x * P0.x + P0.y * P0.y + P1.x * P1.x + P1.y * P1.y
                     + P2.x * P2.x + P2.y * P2.y + P3.x * P3.x + P3.y * P3.y;
                __half2 h0 = __float22half2_rn(P0);
                __half2 h1 = __float22half2_rn(P1);
                __half2 h2 = __float22half2_rn(P2);
                __half2 h3 = __float22half2_rn(P3);
                int chunk = h * 4 + c2 * 2 + ky2;
                uint32_t off = SWZ((uint32_t)(p * 128 + chunk * 16));
                *reinterpret_cast<uint4*>(smem + SM_A + off) =
                    make_uint4(*reinterpret_cast<uint32_t*>(&h0),
                               *reinterpret_cast<uint32_t*>(&h1),
                               *reinterpret_cast<uint32_t*>(&h2),
                               *reinterpret_cast<uint32_t*>(&h3));
            }
        }
        ssq += __shfl_xor_sync(0xffffffffu, ssq, 1);
        if (h == 0) sSsq[p] = ssq;
    }
    PAIR_BAR(1 + pair);    // pair-scoped: A rows [32*pair, +32) ready

    // ---- GEMM: warp (mi,ni): rows [32mi,32mi+32), cols [64ni,64ni+64) ----
    const int L   = tid & 31;
    const int wid = tid >> 5;
    const int mi  = wid >> 1;          // == pair
    const int ni  = wid & 1;           // 0..1

    float acc[2][8][4];
    #pragma unroll
    for (int mt = 0; mt < 2; mt++)
        #pragma unroll
        for (int nt = 0; nt < 8; nt++)
            #pragma unroll
            for (int r = 0; r < 4; r++) acc[mt][nt][r] = 0.f;

    {
        const uint32_t aRow = (uint32_t)(mi * 32 + (L & 7) + (((L >> 3) & 1) << 3));
        const uint32_t aCh  = (L >> 4) & 1;
        const uint4* bfp = g_Bfrag + (ni * 4) * 4 * 32 + L;

        #pragma unroll
        for (int k = 0; k < 4; k++) {
            uint32_t ah[2][4];
            #pragma unroll
            for (int mt = 0; mt < 2; mt++) {
                uint32_t off = SWZ((aRow + mt * 16) * 128 + (2 * k + aCh) * 16);
                ldmx4(ah[mt], sb + SM_A + off);
            }
            #pragma unroll
            for (int bt = 0; bt < 4; bt++) {
                uint4 bq = bfp[(k * 4 + bt) * 32];
                const uint32_t* bf = reinterpret_cast<const uint32_t*>(&bq);
                #pragma unroll
                for (int mt = 0; mt < 2; mt++)
                    #pragma unroll
                    for (int n2 = 0; n2 < 2; n2++) {
                        int nt = bt * 2 + n2;
                        mma_f16(acc[mt][nt], ah[mt], bf + 2 * n2);
                    }
            }
        }
    }

    // ---- epilogue: per thread 4 rows; state s = 32ni + 4nt + qd ----
    const int g  = L >> 2;
    const int qd = L & 3;
    #pragma unroll
    for (int mt = 0; mt < 2; mt++) {
        #pragma unroll
        for (int rh = 0; rh < 2; rh++) {
            float pr[8];
            #pragma unroll
            for (int nt = 0; nt < 8; nt++) {
                float re = acc[mt][nt][rh * 2 + 0];
                float im = acc[mt][nt][rh * 2 + 1];
                pr[nt] = re * re + im * im;
            }
            float e0 = pr[0] + pr[4], e1 = pr[1] + pr[5];
            float e2 = pr[2] + pr[6], e3 = pr[3] + pr[7];
            float d0 = pr[0] - pr[4], d1 = pr[1] - pr[5];
            float d2 = pr[2] - pr[6], d3 = pr[3] - pr[7];
            float z1 = (d0 + d1) + (d2 + d3);
            float f0 = e0 + e2, f1 = e1 + e3;
            float qt = f0 + f1;
            float z3 = f0 - f1;
            float z2 = (e0 - e2) + (e1 - e3);

            float W = qt;
            #pragma unroll
            for (int m = 1; m <= 2; m <<= 1) {
                float tt = __shfl_xor_sync(0xffffffffu, W, m);
                W = (L & m) ? (tt - W) : (W + tt);
            }
            z1 += __shfl_xor_sync(0xffffffffu, z1, 1);
            z1 += __shfl_xor_sync(0xffffffffu, z1, 2);
            z2 += __shfl_xor_sync(0xffffffffu, z2, 1);
            z2 += __shfl_xor_sync(0xffffffffu, z2, 2);
            z3 += __shfl_xor_sync(0xffffffffu, z3, 1);
            z3 += __shfl_xor_sync(0xffffffffu, z3, 2);

            int row = mi * 32 + mt * 16 + rh * 8 + g;
            float* dst = sZ + (ni * 64 + row) * 6;
            if (qd == 0) { dst[0] = W; dst[1] = z1; dst[2] = z2; dst[3] = z3; }
            else if (qd == 1) dst[5] = W;
            else if (qd == 2) dst[4] = W;
        }
    }
    PAIR_BAR(1 + pair);    // pair-scoped: sZ rows [32*pair, +32) ready

    // ---- merge halves + normalize + store (pair-local: 32 rows x 6 qubits) --
    {
        const int q    = tid & 63;
        const int row  = pair * 32 + (q & 31);
        const int qb0  = q >> 5;               // 0..1
        const int pi   = blockIdx.x * 64 + row;
        const int b    = pi / OHW;
        const int rem  = pi - b * OHW;
        const float inv = 1.f / sSsq[row];
        float* obase = out + b * 6 * OHW + rem;
        const float* z0p = sZ + row * 6;
        const float* z1p = sZ + (64 + row) * 6;
        #pragma unroll
        for (int half = 0; half < 3; half++) {
            int qb = qb0 + 2 * half;           // {0,1}+{0,2,4} -> 0..5
            float a0 = z0p[qb];
            float a1 = z1p[qb];
            float zv = (qb == 0) ? (a0 - a1) : (a0 + a1);
            obase[qb * OHW] = zv * inv;
        }
    }
}

// ----------------------------------------------------------------------------
extern "C" void kernel_launch(void* const* d_in, const int* in_sizes, int n_in,
                              void* d_out, int out_size) {
    const float* x = (const float*)d_in[0];      // (128, 4, 128, 128) f32
    const float* w = (const float*)d_in[1];      // (2, 6, 3) f32
    float* out = (float*)d_out;                  // (128, 6, 63, 63) f32
    (void)in_sizes; (void)n_in; (void)out_size;

    cudaFuncSetAttribute(qconv_kernel, cudaFuncAttributeMaxDynamicSharedMemorySize, SM_TOTAL);
    build_unitary_kernel<<<4, 512>>>(w);
    qconv_kernel<<<NPATCH / 64, 128, SM_TOTAL>>>(x, out);
}

// round 17
// speedup vs baseline: 1.0513x; 1.0513x over previous
#include <cuda_runtime.h>
#include <cuda_fp16.h>
#include <cstdint>

// ============================================================================
// QConv2D quantum conv via baseline-PTX fp16 mma.sync (HMMA) GEMM.
//   Kernel 1 (grid 4 x 512): build 64x64 unitary U (register statevector,
//   warp per column), emit B[128x64] fp16 PRE-PACKED in mma fragment layout.
//   B rows interleaved: 2s=Re U[s,:], 2s+1=Im U[s,:].
//   Kernel 2 (CTA = 64 patches, 128 threads, 5 CTAs/SM): A = patch fp16 via
//   smem+ldmatrix; B fragments via direct LDG.128 (L1-resident, batched per
//   k-step). C[64x128] = A*B^T (fp32 accum). Epilogue: probs, factorized
//   Walsh with BATCHED cross-block shuffles (latency-hidden), deferred
//   normalization by ||f||^2.
// ============================================================================

#define N_QUBITS 6
#define OH 63
#define OHW 3969
#define NPATCH (128 * OHW)     // 508032
#define SWZ(o) ((o) ^ (((o) >> 3) & 0x70))

__device__ uint4 g_Bfrag[1024];   // [ni][k][bt][lane] -> 16 KB

__device__ __forceinline__ uint32_t smem_u32(const void* p) {
    uint32_t a;
    asm("{ .reg .u64 t; cvta.to.shared.u64 t, %1; cvt.u32.u64 %0, t; }"
        : "=r"(a) : "l"(p));
    return a;
}
__device__ __forceinline__ void ldmx4(uint32_t* r, uint32_t addr) {
    asm volatile("ldmatrix.sync.aligned.m8n8.x4.shared.b16 {%0,%1,%2,%3}, [%4];"
                 : "=r"(r[0]), "=r"(r[1]), "=r"(r[2]), "=r"(r[3]) : "r"(addr));
}
__device__ __forceinline__ void mma_f16(float* c, const uint32_t* a, const uint32_t* b) {
    asm volatile(
        "mma.sync.aligned.m16n8k16.row.col.f32.f16.f16.f32 "
        "{%0,%1,%2,%3}, {%4,%5,%6,%7}, {%8,%9}, {%0,%1,%2,%3};"
        : "+f"(c[0]), "+f"(c[1]), "+f"(c[2]), "+f"(c[3])
        : "r"(a[0]), "r"(a[1]), "r"(a[2]), "r"(a[3]), "r"(b[0]), "r"(b[1]));
}
__device__ __forceinline__ float2 cmad(float2 u, float2 a, float2 v, float2 b) {
    float2 r;
    r.x = u.x * a.x - u.y * a.y + v.x * b.x - v.y * b.y;
    r.y = u.x * a.y + u.y * a.x + v.x * b.y + v.y * b.x;
    return r;
}

// ----------------------------------------------------------------------------
// Kernel 1: build U + emit fragment-packed B.
// grid=4 (one per 16-col k-chunk), block=512 (16 warps = 16 columns).
// ----------------------------------------------------------------------------
__global__ __launch_bounds__(512) void build_unitary_kernel(const float* __restrict__ w) {
    __shared__ float gt[12][8];
    __shared__ __half sBL[128][17];   // [B row n][k local 0..15], padded
    const int t = threadIdx.x;
    if (t < 12) {
        int l = t / 6, q = t % 6;
        float phi   = w[(l * 6 + q) * 3 + 0];
        float theta = w[(l * 6 + q) * 3 + 1];
        float omega = w[(l * 6 + q) * 3 + 2];
        float s2, c2; sincosf(0.5f * theta, &s2, &c2);
        float sap, cap; sincosf(-0.5f * (phi + omega), &sap, &cap);
        float sam, cam; sincosf(-0.5f * (phi - omega), &sam, &cam);
        gt[t][0] =  cap * c2; gt[t][1] =  sap * c2;   // u00
        gt[t][2] = -cam * s2; gt[t][3] =  sam * s2;   // u01
        gt[t][4] =  cam * s2; gt[t][5] =  sam * s2;   // u10
        gt[t][6] =  cap * c2; gt[t][7] = -sap * c2;   // u11
    }
    __syncthreads();

    const int lane = t & 31;
    const int wid  = t >> 5;                  // local column 0..15
    const int col  = blockIdx.x * 16 + wid;   // global column (k index)

    float2 s0 = make_float2((2 * lane     == col) ? 1.f : 0.f, 0.f);
    float2 s1 = make_float2((2 * lane + 1 == col) ? 1.f : 0.f, 0.f);

    for (int rep = 0; rep < 2; rep++) {
        for (int l = 0; l < 2; l++) {
            for (int q = 0; q < N_QUBITS; q++) {
                const float* g = gt[l * 6 + q];
                float2 u00 = {g[0], g[1]}, u01 = {g[2], g[3]};
                float2 u10 = {g[4], g[5]}, u11 = {g[6], g[7]};
                int m = 1 << (5 - q);
                if (m == 1) {
                    float2 a = s0, b = s1;
                    s0 = cmad(u00, a, u01, b);
                    s1 = cmad(u10, a, u11, b);
                } else {
                    int d = m >> 1;
                    float2 p0, p1;
                    p0.x = __shfl_xor_sync(0xffffffffu, s0.x, d);
                    p0.y = __shfl_xor_sync(0xffffffffu, s0.y, d);
                    p1.x = __shfl_xor_sync(0xffffffffu, s1.x, d);
                    p1.y = __shfl_xor_sync(0xffffffffu, s1.y, d);
                    if (lane & d) {
                        s0 = cmad(u10, p0, u11, s0);
                        s1 = cmad(u10, p1, u11, s1);
                    } else {
                        s0 = cmad(u00, s0, u01, p0);
                        s1 = cmad(u00, s1, u01, p1);
                    }
                }
            }
            int r = l + 1;
            for (int q = 0; q < N_QUBITS; q++) {
                int tq = (q + r) % N_QUBITS;
                int mc = 1 << (5 - q);
                int mt = 1 << (5 - tq);
                if (mt == 1) {
                    if (lane & (mc >> 1)) { float2 tmp = s0; s0 = s1; s1 = tmp; }
                } else {
                    int d = mt >> 1;
                    if (mc == 1) {
                        float2 t1;
                        t1.x = __shfl_xor_sync(0xffffffffu, s1.x, d);
                        t1.y = __shfl_xor_sync(0xffffffffu, s1.y, d);
                        s1 = t1;
                    } else {
                        float2 t0, t1;
                        t0.x = __shfl_xor_sync(0xffffffffu, s0.x, d);
                        t0.y = __shfl_xor_sync(0xffffffffu, s0.y, d);
                        t1.x = __shfl_xor_sync(0xffffffffu, s1.x, d);
                        t1.y = __shfl_xor_sync(0xffffffffu, s1.y, d);
                        if (lane & (mc >> 1)) { s0 = t0; s1 = t1; }
                    }
                }
            }
        }
    }
    // B rows: n = 2s + (0:Re, 1:Im); lane holds states 2L, 2L+1
    sBL[4 * lane + 0][wid] = __float2half(s0.x);
    sBL[4 * lane + 1][wid] = __float2half(s0.y);
    sBL[4 * lane + 2][wid] = __float2half(s1.x);
    sBL[4 * lane + 3][wid] = __float2half(s1.y);
    __syncthreads();

    // emit fragments for this k-chunk (kc = blockIdx.x): 256 uint4
    if (t < 256) {
        const int L  = t & 31;
        const int bt = (t >> 5) & 3;
        const int ni = t >> 7;
        const int kc = blockIdx.x;
        const int n0 = ni * 64 + bt * 16 + (L >> 2);
        const int kk = 2 * (L & 3);
        __half2 b0t0 = {sBL[n0][kk],         sBL[n0][kk + 1]};
        __half2 b1t0 = {sBL[n0][kk + 8],     sBL[n0][kk + 9]};
        __half2 b0t1 = {sBL[n0 + 8][kk],     sBL[n0 + 8][kk + 1]};
        __half2 b1t1 = {sBL[n0 + 8][kk + 8], sBL[n0 + 8][kk + 9]};
        g_Bfrag[((ni * 4 + kc) * 4 + bt) * 32 + L] =
            make_uint4(*reinterpret_cast<uint32_t*>(&b0t0),
                       *reinterpret_cast<uint32_t*>(&b1t0),
                       *reinterpret_cast<uint32_t*>(&b0t1),
                       *reinterpret_cast<uint32_t*>(&b1t1));
    }
}

// ----------------------------------------------------------------------------
// Kernel 2: HMMA GEMM + epilogue. 128 threads (4 warps, 2x2 tile grid),
// 64 patches per CTA, 5 CTAs/SM. B fragments via direct LDG.128.
// ----------------------------------------------------------------------------
#define SM_A  0            //  8 KB: 64 rows x 128 B
#define SM_SSQ 8192        // float[64] = 256 B
#define SM_SZ  8448        // float[2][64][6] = 3072 B
#define SM_TOTAL 11520

__global__ __launch_bounds__(128, 5)
void qconv_kernel(const float* __restrict__ x, float* __restrict__ out) {
    extern __shared__ char smem[];
    const uint32_t sb = smem_u32(smem);
    float* sSsq = reinterpret_cast<float*>(smem + SM_SSQ);
    float* sZ   = reinterpret_cast<float*>(smem + SM_SZ);   // [ni][row][6]
    const int tid = threadIdx.x;

    // ---- load phase: thread = (patch p = tid>>1, half h = tid&1 -> 2 channels)
    {
        const int p  = tid >> 1;              // 0..63
        const int h  = tid & 1;
        const int pi = blockIdx.x * 64 + p;
        const int b   = pi / OHW;
        const int rem = pi - b * OHW;
        const int oy  = rem / OH;
        const int ox  = rem - oy * OH;
        const float* xb = x + (((b * 4 + 2 * h) * 128) + 2 * oy) * 128 + 2 * ox;

        float ssq = 0.f;
        #pragma unroll
        for (int c2 = 0; c2 < 2; c2++) {
            #pragma unroll
            for (int ky2 = 0; ky2 < 2; ky2++) {
                const float* rA = xb + c2 * 16384 + (2 * ky2) * 128;
                float2 P0 = *reinterpret_cast<const float2*>(rA);
                float2 P1 = *reinterpret_cast<const float2*>(rA + 2);
                float2 P2 = *reinterpret_cast<const float2*>(rA + 128);
                float2 P3 = *reinterpret_cast<const float2*>(rA + 130);
                ssq += P0.x * P0.x + P0.y * P0.y + P1.x * P1.x + P1.y * P1.y
                     + P2.x * P2.x + P2.y * P2.y + P3.x * P3.x + P3.y * P3.y;
                __half2 h0 = __float22half2_rn(P0);
                __half2 h1 = __float22half2_rn(P1);
                __half2 h2 = __float22half2_rn(P2);
                __half2 h3 = __float22half2_rn(P3);
                int chunk = h * 4 + c2 * 2 + ky2;
                uint32_t off = SWZ((uint32_t)(p * 128 + chunk * 16));
                *reinterpret_cast<uint4*>(smem + SM_A + off) =
                    make_uint4(*reinterpret_cast<uint32_t*>(&h0),
                               *reinterpret_cast<uint32_t*>(&h1),
                               *reinterpret_cast<uint32_t*>(&h2),
                               *reinterpret_cast<uint32_t*>(&h3));
            }
        }
        ssq += __shfl_xor_sync(0xffffffffu, ssq, 1);
        if (h == 0) sSsq[p] = ssq;
    }
    __syncthreads();

    // ---- GEMM: warp (mi,ni): rows [32mi,32mi+32), cols [64ni,64ni+64) ----
    const int L   = tid & 31;
    const int wid = tid >> 5;
    const int mi  = wid >> 1;          // 0..1
    const int ni  = wid & 1;           // 0..1

    float acc[2][8][4];
    #pragma unroll
    for (int mt = 0; mt < 2; mt++)
        #pragma unroll
        for (int nt = 0; nt < 8; nt++)
            #pragma unroll
            for (int r = 0; r < 4; r++) acc[mt][nt][r] = 0.f;

    {
        const uint32_t aRow = (uint32_t)(mi * 32 + (L & 7) + (((L >> 3) & 1) << 3));
        const uint32_t aCh  = (L >> 4) & 1;
        const uint4* bfp = g_Bfrag + (ni * 4) * 4 * 32 + L;

        #pragma unroll
        for (int k = 0; k < 4; k++) {
            // batch all B LDGs for this k first (latency hides under LDSM/MMA)
            uint4 bq[4];
            #pragma unroll
            for (int bt = 0; bt < 4; bt++) bq[bt] = bfp[(k * 4 + bt) * 32];
            uint32_t ah[2][4];
            #pragma unroll
            for (int mt = 0; mt < 2; mt++) {
                uint32_t off = SWZ((aRow + mt * 16) * 128 + (2 * k + aCh) * 16);
                ldmx4(ah[mt], sb + SM_A + off);
            }
            #pragma unroll
            for (int bt = 0; bt < 4; bt++) {
                const uint32_t* bf = reinterpret_cast<const uint32_t*>(&bq[bt]);
                #pragma unroll
                for (int mt = 0; mt < 2; mt++)
                    #pragma unroll
                    for (int n2 = 0; n2 < 2; n2++) {
                        int nt = bt * 2 + n2;
                        mma_f16(acc[mt][nt], ah[mt], bf + 2 * n2);
                    }
            }
        }
    }

    // ---- epilogue: 4 blocks (mt,rh); batched reductions then batched shfls --
    const int g  = L >> 2;
    const int qd = L & 3;
    float Wv[4], z1v[4], z2v[4], z3v[4];
    #pragma unroll
    for (int blk = 0; blk < 4; blk++) {
        const int mt = blk >> 1;
        const int rh = blk & 1;
        float pr[8];
        #pragma unroll
        for (int nt = 0; nt < 8; nt++) {
            float re = acc[mt][nt][rh * 2 + 0];
            float im = acc[mt][nt][rh * 2 + 1];
            pr[nt] = re * re + im * im;
        }
        float e0 = pr[0] + pr[4], e1 = pr[1] + pr[5];
        float e2 = pr[2] + pr[6], e3 = pr[3] + pr[7];
        float d0 = pr[0] - pr[4], d1 = pr[1] - pr[5];
        float d2 = pr[2] - pr[6], d3 = pr[3] - pr[7];
        z1v[blk] = (d0 + d1) + (d2 + d3);
        float f0 = e0 + e2, f1 = e1 + e3;
        Wv[blk]  = f0 + f1;               // qt
        z3v[blk] = f0 - f1;
        z2v[blk] = (e0 - e2) + (e1 - e3);
    }
    // stage 1 (mask 1): all 16 shuffles independent
    #pragma unroll
    for (int blk = 0; blk < 4; blk++) {
        float tW = __shfl_xor_sync(0xffffffffu, Wv[blk], 1);
        Wv[blk] = (L & 1) ? (tW - Wv[blk]) : (Wv[blk] + tW);
        z1v[blk] += __shfl_xor_sync(0xffffffffu, z1v[blk], 1);
        z2v[blk] += __shfl_xor_sync(0xffffffffu, z2v[blk], 1);
        z3v[blk] += __shfl_xor_sync(0xffffffffu, z3v[blk], 1);
    }
    // stage 2 (mask 2)
    #pragma unroll
    for (int blk = 0; blk < 4; blk++) {
        float tW = __shfl_xor_sync(0xffffffffu, Wv[blk], 2);
        Wv[blk] = (L & 2) ? (tW - Wv[blk]) : (Wv[blk] + tW);
        z1v[blk] += __shfl_xor_sync(0xffffffffu, z1v[blk], 2);
        z2v[blk] += __shfl_xor_sync(0xffffffffu, z2v[blk], 2);
        z3v[blk] += __shfl_xor_sync(0xffffffffu, z3v[blk], 2);
    }
    // writers: lane qd=0 -> {q0,q1,q2,q3}; qd=1 -> q5; qd=2 -> q4
    #pragma unroll
    for (int blk = 0; blk < 4; blk++) {
        const int mt = blk >> 1;
        const int rh = blk & 1;
        int row = mi * 32 + mt * 16 + rh * 8 + g;
        float* dst = sZ + (ni * 64 + row) * 6;
        if (qd == 0) { dst[0] = Wv[blk]; dst[1] = z1v[blk]; dst[2] = z2v[blk]; dst[3] = z3v[blk]; }
        else if (qd == 1) dst[5] = Wv[blk];
        else if (qd == 2) dst[4] = Wv[blk];
    }
    __syncthreads();

    // ---- merge halves + normalize + store (384 outputs, 128 threads) ----
    {
        const int row0 = tid & 63;
        const int pi   = blockIdx.x * 64 + row0;
        const int b    = pi / OHW;
        const int rem  = pi - b * OHW;
        const float inv = 1.f / sSsq[row0];
        float* obase = out + b * 6 * OHW + rem;
        #pragma unroll
        for (int half = 0; half < 3; half++) {
            int qb = (tid + half * 128) >> 6;   // 0..5
            float a0 = sZ[row0 * 6 + qb];
            float a1 = sZ[(64 + row0) * 6 + qb];
            float zv = (qb == 0) ? (a0 - a1) : (a0 + a1);
            obase[qb * OHW] = zv * inv;
        }
    }
}

// ----------------------------------------------------------------------------
extern "C" void kernel_launch(void* const* d_in, const int* in_sizes, int n_in,
                              void* d_out, int out_size) {
    const float* x = (const float*)d_in[0];      // (128, 4, 128, 128) f32
    const float* w = (const float*)d_in[1];      // (2, 6, 3) f32
    float* out = (float*)d_out;                  // (128, 6, 63, 63) f32
    (void)in_sizes; (void)n_in; (void)out_size;

    cudaFuncSetAttribute(qconv_kernel, cudaFuncAttributeMaxDynamicSharedMemorySize, SM_TOTAL);
    build_unitary_kernel<<<4, 512>>>(w);
    qconv_kernel<<<NPATCH / 64, 128, SM_TOTAL>>>(x, out);
}